// round 11
// baseline (speedup 1.0000x reference)
#include <cuda_runtime.h>
#include <cuda_fp16.h>
#include <cstdint>
#include <math.h>

#define V   32000
#define D   256
#define UH  512
#define BB  16
#define TT  128
#define NS  126
#define G4  2048
#define OROWS (BB*NS)
#define OC  1024
#define NBLK 128
#define NSTEP 127

typedef unsigned long long ull;

// ---------------- device scratch ----------------
__device__ float g_emb[BB*TT*D];
__device__ float g_X[2][NS*BB*G4];
__device__ float g_h0t[2][2][UH*BB];
__device__ float g_h1t[2][2][UH*BB];
__device__ unsigned g_cnt2[2*32];
__device__ volatile unsigned g_gen2[2*32];
__device__ __half A_h[(size_t)2048*1024];     // [m][k]
__device__ __half B_h[(size_t)32000*1024];    // [n][k] (Wp^T)

// ---------------- f32x2 helpers ----------------
__device__ __forceinline__ ull pack2(float lo, float hi){
    ull r;
    asm("mov.b64 %0, {%1,%2};" : "=l"(r)
        : "r"(__float_as_uint(lo)), "r"(__float_as_uint(hi)));
    return r;
}
__device__ __forceinline__ void unpack2(ull v, float& lo, float& hi){
    unsigned a, b;
    asm("mov.b64 {%0,%1}, %2;" : "=r"(a), "=r"(b) : "l"(v));
    lo = __uint_as_float(a); hi = __uint_as_float(b);
}
__device__ __forceinline__ ull ffma2(ull a, ull b, ull c){
    ull r;
    asm("fma.rn.f32x2 %0, %1, %2, %3;" : "=l"(r) : "l"(a), "l"(b), "l"(c));
    return r;
}
__device__ __forceinline__ float sigf(float x){ return 1.f/(1.f + __expf(-x)); }
__device__ __forceinline__ float tanhfast(float x){ return 2.f/(1.f + __expf(-2.f*x)) - 1.f; }

// ---------------- arch-neutral PTX helpers ----------------
__device__ __forceinline__ uint32_t smem_u32(const void* p){
    uint32_t a;
    asm("{ .reg .u64 t; cvta.to.shared.u64 t, %1; cvt.u32.u64 %0, t; }" : "=r"(a) : "l"(p));
    return a;
}
__device__ __forceinline__ void cpa16(uint32_t s, const void* g){
    asm volatile("cp.async.cg.shared.global [%0], [%1], 16;" :: "r"(s), "l"(g) : "memory");
}
#define CPA_COMMIT() asm volatile("cp.async.commit_group;" ::: "memory")
#define CPA_WAIT1()  asm volatile("cp.async.wait_group 1;" ::: "memory")
#define CPA_WAIT0()  asm volatile("cp.async.wait_group 0;" ::: "memory")

#define LDSM_X4(r0,r1,r2,r3,addr) \
    asm volatile("ldmatrix.sync.aligned.m8n8.x4.shared.b16 {%0,%1,%2,%3}, [%4];" \
        : "=r"(r0), "=r"(r1), "=r"(r2), "=r"(r3) : "r"(addr))
#define LDSM_X2(r0,r1,addr) \
    asm volatile("ldmatrix.sync.aligned.m8n8.x2.shared.b16 {%0,%1}, [%2];" \
        : "=r"(r0), "=r"(r1) : "r"(addr))
#define MMA16816(c,a,b) \
    asm volatile("mma.sync.aligned.m16n8k16.row.col.f32.f16.f16.f32 " \
        "{%0,%1,%2,%3}, {%4,%5,%6,%7}, {%8,%9}, {%0,%1,%2,%3};" \
        : "+f"((c)[0]), "+f"((c)[1]), "+f"((c)[2]), "+f"((c)[3]) \
        : "r"((a)[0]), "r"((a)[1]), "r"((a)[2]), "r"((a)[3]), \
          "r"((b)[0]), "r"((b)[1]))

// ---------------- init (every replay) ----------------
__global__ void k_init(){
    int i = blockIdx.x*blockDim.x + threadIdx.x;
    int n = 2*2*UH*BB;
    if (i < n){
        ((float*)g_h0t)[i] = 0.f;
        ((float*)g_h1t)[i] = 0.f;
    }
    if (i < 64){ g_cnt2[i] = 0u; g_gen2[i] = 0u; }
}

// ---------------- embedding gather ----------------
__global__ void k_embed(const int* __restrict__ seqs, const float* __restrict__ embed){
    int i = blockIdx.x*blockDim.x + threadIdx.x;
    if (i >= BB*TT*(D/4)) return;
    int bt = i / (D/4);
    int d4 = i % (D/4);
    int tok = seqs[bt];
    float4 v = *(const float4*)&embed[(size_t)tok*D + d4*4];
    *(float4*)&g_emb[(size_t)bt*D + d4*4] = v;
}

// ---------------- X precompute GEMM (fp32 FFMA2) ----------------
__global__ __launch_bounds__(256) void k_xprep(const float* __restrict__ fW0,
                                               const float* __restrict__ fb0,
                                               const float* __restrict__ bW0,
                                               const float* __restrict__ bb0){
    const int dir = blockIdx.z;
    const float* W    = dir ? bW0 : fW0;
    const float* bias = dir ? bb0 : fb0;
    float* out = g_X[dir];
    const int m0 = blockIdx.y*128, n0 = blockIdx.x*256;
    __shared__ float As[16][128];
    __shared__ float Bs[16][256];
    const int tid = threadIdx.x;
    const int tx = tid & 15, ty = tid >> 4;

    ull acc[8][8];
    #pragma unroll
    for (int i=0;i<8;i++)
        #pragma unroll
        for (int q=0;q<8;q++) acc[i][q] = 0ull;

    for (int kt=0; kt<16; kt++){
        #pragma unroll
        for (int i=0;i<2;i++){
            int lin = tid + i*256;
            int row = lin>>2, c4 = lin&3;
            int r = m0 + row;
            float4 v = make_float4(0.f,0.f,0.f,0.f);
            if (r < OROWS){
                int t = r>>4, b = r&15;
                int txi = dir ? (127 - t) : t;
                v = *(const float4*)&g_emb[((b<<7)+txi)*D + kt*16 + c4*4];
            }
            As[c4*4+0][row]=v.x; As[c4*4+1][row]=v.y;
            As[c4*4+2][row]=v.z; As[c4*4+3][row]=v.w;
        }
        #pragma unroll
        for (int i=0;i<4;i++){
            int lin = tid + i*256;
            int kr = lin>>6, c4 = lin&63;
            *(float4*)&Bs[kr][c4*4] =
                *(const float4*)&W[(size_t)(kt*16+kr)*G4 + n0 + c4*4];
        }
        __syncthreads();
        #pragma unroll
        for (int k=0;k<16;k++){
            float a0[8];
            *(float4*)&a0[0] = *(float4*)&As[k][ty*8];
            *(float4*)&a0[4] = *(float4*)&As[k][ty*8+4];
            ull av[8];
            #pragma unroll
            for (int i=0;i<8;i++) av[i] = pack2(a0[i], a0[i]);
            ull bv[8];
            #pragma unroll
            for (int q=0;q<4;q++){
                ulonglong2 p = *(const ulonglong2*)&Bs[k][tx*16 + q*4];
                bv[2*q] = p.x; bv[2*q+1] = p.y;
            }
            #pragma unroll
            for (int i=0;i<8;i++)
                #pragma unroll
                for (int q=0;q<8;q++)
                    acc[i][q] = ffma2(av[i], bv[q], acc[i][q]);
        }
        __syncthreads();
    }
    #pragma unroll
    for (int i=0;i<8;i++){
        int r = m0 + ty*8 + i;
        if (r >= OROWS) continue;
        float* crow = out + (size_t)r*G4 + n0 + tx*16;
        #pragma unroll
        for (int q=0;q<8;q++){
            float lo,hi; unpack2(acc[i][q], lo, hi);
            int col = n0 + tx*16 + 2*q;
            float2 st; st.x = lo + bias[col]; st.y = hi + bias[col+1];
            *(float2*)&crow[2*q] = st;
        }
    }
}

// ---------------- persistent recurrence: 512 threads, col-pair f32x2 ----------------
// SMEM: wsQ [8 cq][1025 k] float4 (131200B), ht0/ht1 [512][16] (2x32KB),
//       zpA/zpB [kg 8][cpg 16][b 16] ull (2x16KB), c-state 1KB
#define WSQ_FL   (8*1025*4)
#define HT_FL    (UH*BB)
#define ZP_FL    (8*16*16*2)
#define RSMEM_FL (WSQ_FL + 2*HT_FL + 2*ZP_FL + 256)

__global__ __launch_bounds__(512,1) void k_recur(
    const float* __restrict__ fU0, const float* __restrict__ fW1,
    const float* __restrict__ fU1, const float* __restrict__ fb1,
    const float* __restrict__ bU0, const float* __restrict__ bW1,
    const float* __restrict__ bU1, const float* __restrict__ bb1,
    const int*   __restrict__ seqs)
{
    extern __shared__ float sm[];
    float* wsQ  = sm;
    float* ht0s = sm + WSQ_FL;
    float* ht1s = ht0s + HT_FL;
    float* zpAf = ht1s + HT_FL;                // [kg][cpg][b] as ull (col-pair)
    float* zpBf = zpAf + ZP_FL;
    float* c0s  = zpBf + ZP_FL;
    float* c1s  = c0s + 128;
    ull* zpAu = (ull*)zpAf;
    ull* zpBu = (ull*)zpBf;

    const int tid  = threadIdx.x;
    const int wid  = tid >> 5;                 // 0..15
    const int lane = tid & 31;
    const int blk  = blockIdx.x;
    const int dir  = blk >> 6;
    const int u0   = (blk & 63) * 8;

    const float* U0 = dir ? bU0 : fU0;
    const float* W1 = dir ? bW1 : fW1;
    const float* U1 = dir ? bU1 : fU1;
    const float* b1 = dir ? bb1 : fb1;
    const float* Xp = g_X[dir];

    // ---- preload U0|W1 into wsQ (once): wsQ[(cq*1025+k)*4 + c] ----
    for (int idx = tid; idx < 8*1024; idx += 512){
        int cq = idx >> 10, k = idx & 1023;
        int kk = k & 511;
        const float* Wsrc = (k < 512) ? U0 : W1;
        int jb = (cq>>1)*512 + u0 + (cq&1)*4;
        float4 v = *(const float4*)&Wsrc[(size_t)kk*G4 + jb];
        *(float4*)&wsQ[((size_t)cq*1025 + k)*4] = v;
    }
    if (tid < 128){ c0s[tid] = 0.f; c1s[tid] = 0.f; }
    __syncthreads();

    const int kg  = wid & 7;          // k-group
    const int ch  = wid >> 3;         // col half
    const int cql = lane & 3;         // col quad within half
    const int bq  = lane >> 2;        // batch pair 0..7
    const int cq  = ch*4 + cql;       // global col quad 0..7
    const int kbA = kg * 128;         // phase A weight k-range
    const int kA0 = kbA & 511;        // phase A h-index (both halves read ht0s)
    const int kbB = kg * 64;          // phase B k-range
    const float* wA  = wsQ + ((size_t)cq*1025 + kbA)*4;
    const float* UgB = U1 + (size_t)((cq>>1)*512 + u0 + (cq&1)*4);
    const uint32_t d0s = smem_u32(ht0s);
    const uint32_t d1s = smem_u32(ht1s);
    unsigned* cnt = &g_cnt2[dir*32];
    volatile unsigned* gen = &g_gen2[dir*32];

    for (int s = 0; s < NSTEP; s++){
        // ---- async-stage h0[s-1] (group A) and h1[s-2] (group B) ----
        {
            const float4* s0 = (const float4*)g_h0t[dir][(s+1)&1];
            const float4* s1 = (const float4*)g_h1t[dir][s&1];
            #pragma unroll
            for (int i=0;i<4;i++){ int ix = tid + i*512; cpa16(d0s + ix*16, s0+ix); }
            CPA_COMMIT();
            #pragma unroll
            for (int i=0;i<4;i++){ int ix = tid + i*512; cpa16(d1s + ix*16, s1+ix); }
            CPA_COMMIT();
        }

        // phase-B U1 group-0 prefetch (hides under staging + phase A)
        ulonglong2 wb0[8], wb1[8];
        #pragma unroll
        for (int i=0;i<8;i++)
            wb0[i] = __ldcg((const ulonglong2*)(UgB + (size_t)(kbB+i)*G4));

        CPA_WAIT1();
        __syncthreads();

        // ---- phase A: U0|W1 (smem weights as col-pairs), h0 broadcast ----
        ull accA[2][2];
        accA[0][0]=0ull; accA[0][1]=0ull; accA[1][0]=0ull; accA[1][1]=0ull;
        {
            const float* hp = ht0s + (size_t)kA0*16 + 2*bq;
            #pragma unroll 8
            for (int k=0;k<128;k++){
                ulonglong2 wv = *(const ulonglong2*)(wA + (size_t)k*4);
                float2 h2 = *(const float2*)(hp + (size_t)k*16);
                ull hx = pack2(h2.x,h2.x), hy = pack2(h2.y,h2.y);
                accA[0][0]=ffma2(wv.x,hx,accA[0][0]); accA[0][1]=ffma2(wv.x,hy,accA[0][1]);
                accA[1][0]=ffma2(wv.y,hx,accA[1][0]); accA[1][1]=ffma2(wv.y,hy,accA[1][1]);
            }
        }

        CPA_WAIT0();
        __syncthreads();

        // ---- phase B: U1 (gmem stream as col-pairs), h1 broadcast ----
        ull accB[2][2];
        accB[0][0]=0ull; accB[0][1]=0ull; accB[1][0]=0ull; accB[1][1]=0ull;
        #pragma unroll
        for (int i=0;i<8;i++)
            wb1[i] = __ldcg((const ulonglong2*)(UgB + (size_t)(kbB+8+i)*G4));
        {
            const float* hp = ht1s + 2*bq;
            #pragma unroll
            for (int g=0; g<8; g++){
                #pragma unroll
                for (int i=0;i<8;i++){
                    int k = kbB + g*8 + i;
                    ulonglong2 wv = (g&1) ? wb1[i] : wb0[i];
                    float2 h2 = *(const float2*)(hp + (size_t)k*16);
                    ull hx = pack2(h2.x,h2.x), hy = pack2(h2.y,h2.y);
                    accB[0][0]=ffma2(wv.x,hx,accB[0][0]); accB[0][1]=ffma2(wv.x,hy,accB[0][1]);
                    accB[1][0]=ffma2(wv.y,hx,accB[1][0]); accB[1][1]=ffma2(wv.y,hy,accB[1][1]);
                    if (g < 6){
                        if (g&1) wb1[i] = __ldcg((const ulonglong2*)(UgB + (size_t)(k+16)*G4));
                        else     wb0[i] = __ldcg((const ulonglong2*)(UgB + (size_t)(k+16)*G4));
                    }
                }
            }
        }

        // ---- write partials: zp[kg][cpg][b], ull = (col_even, col_odd) ----
        #pragma unroll
        for (int cp=0;cp<2;cp++){
            int cpg = cq*2 + cp;
            #pragma unroll
            for (int bb=0;bb<2;bb++){
                int b = 2*bq + bb;
                zpAu[((size_t)kg*16 + cpg)*16 + b] = accA[cp][bb];
                zpBu[((size_t)kg*16 + cpg)*16 + b] = accB[cp][bb];
            }
        }
        __syncthreads();

        // ---- activation / state update (threads 0..255) ----
        if (tid < 256){
            int layer = tid >> 7, id = tid & 127;
            int uu = id >> 4, b = id & 15;
            if (layer == 0){
                if (s < NS){
                    int t = s;
                    float z[4];
                    #pragma unroll
                    for (int g=0; g<4; g++){
                        int col = g*8 + uu, cp = col>>1, par = col&1;
                        float a = Xp[(size_t)((t<<4)+b)*G4 + g*512 + u0 + uu];
                        #pragma unroll
                        for (int w=0; w<4; w++)
                            a += zpAf[(((size_t)w*16 + cp)*16 + b)*2 + par];
                        z[g] = a;
                    }
                    float cold = c0s[id];
                    float cn = sigf(z[1])*cold + sigf(z[0])*tanhfast(z[2]);
                    float hn = sigf(z[3])*tanhfast(cn);
                    int pos = dir ? (127 - t) : t;
                    if (seqs[b*TT + pos] == 0){
                        cn = cold; hn = ht0s[(u0+uu)*16 + b];
                    }
                    c0s[id] = cn;
                    g_h0t[dir][s&1][(u0+uu)*16 + b] = hn;
                }
            } else {
                if (s >= 1){
                    int t = s - 1;
                    float z[4];
                    #pragma unroll
                    for (int g=0; g<4; g++){
                        int col = g*8 + uu, cp = col>>1, par = col&1;
                        float a = b1[g*512 + u0 + uu];
                        #pragma unroll
                        for (int w=4; w<8; w++)
                            a += zpAf[(((size_t)w*16 + cp)*16 + b)*2 + par];
                        #pragma unroll
                        for (int w=0; w<8; w++)
                            a += zpBf[(((size_t)w*16 + cp)*16 + b)*2 + par];
                        z[g] = a;
                    }
                    float cold = c1s[id];
                    float cn = sigf(z[1])*cold + sigf(z[0])*tanhfast(z[2]);
                    float hn = sigf(z[3])*tanhfast(cn);
                    int pos = dir ? (127 - t) : t;
                    if (seqs[b*TT + pos] == 0){
                        cn = cold; hn = ht1s[(u0+uu)*16 + b];
                    }
                    c1s[id] = cn;
                    g_h1t[dir][(s+1)&1][(u0+uu)*16 + b] = hn;
                    int r = dir ? (b*NS + (125 - t)) : (b*NS + t);
                    A_h[(size_t)r*OC + dir*UH + u0 + uu] = __float2half_rn(hn);
                }
            }
        }

        // ---- per-direction grid barrier (64 blocks) ----
        __syncthreads();
        if (tid == 0){
            __threadfence();
            unsigned v = atomicAdd(cnt, 1u) + 1u;
            unsigned tgt = 64u * (unsigned)(s+1);
            if (v == tgt) *gen = (unsigned)(s+1);
            else while (*gen < (unsigned)(s+1)) __nanosleep(64);
        }
        __syncthreads();
    }
}

// ---------------- fp16 pack kernel for B ----------------
__global__ __launch_bounds__(256) void k_splitB(const float* __restrict__ Wp){
    __shared__ float tile[32][33];
    int n0 = blockIdx.x*32, k0 = blockIdx.y*32;
    int tx = threadIdx.x & 31, ty = threadIdx.x >> 5;
    #pragma unroll
    for (int i=0;i<4;i++){
        int k = k0 + ty + i*8;
        tile[ty+i*8][tx] = Wp[(size_t)k*V + n0 + tx];
    }
    __syncthreads();
    #pragma unroll
    for (int i=0;i<4;i++){
        int n = n0 + ty + i*8;
        float x = tile[tx][ty+i*8];
        B_h[(size_t)n*1024 + k0 + tx] = __float2half_rn(x);
    }
}

// ---------------- HMMA projection: single K=1024 GEMM ----------------
#define PBM 256
#define PBN 128
#define PADK 40
#define PA_FL (2*PBM*PADK)
#define PB_FL (2*PBN*PADK)
#define PJ_SMEM ((PA_FL + PB_FL)*2)

__global__ __launch_bounds__(512,1) void k_projhm(const float* __restrict__ bp,
                                                  float* __restrict__ Cout){
    extern __shared__ __half hsm[];
    __half* Asm = hsm;
    __half* Bsm = hsm + PA_FL;

    const int tid  = threadIdx.x;
    const int wid  = tid >> 5;
    const int lane = tid & 31;
    const int m0 = blockIdx.y * PBM, n0 = blockIdx.x * PBN;
    const int wm = (wid & 3) * 64;
    const int wn = (wid >> 2) * 32;

    float acc[4][4][4];
    #pragma unroll
    for (int mf=0; mf<4; mf++)
        #pragma unroll
        for (int nf=0; nf<4; nf++)
            #pragma unroll
            for (int i=0; i<4; i++) acc[mf][nf][i] = 0.f;

    const int arow = tid >> 2, asg = tid & 3;
    const int brow = tid >> 2, bsg = tid & 3;
    uint32_t aDst0 = smem_u32(Asm);
    uint32_t bDst0 = smem_u32(Bsm);

    #define LOAD_CHUNK(buf, kc) do { \
        uint32_t ab = aDst0 + (buf)*PBM*PADK*2; \
        cpa16(ab + (arow*PADK + asg*8)*2, \
              &A_h[(size_t)(m0 + arow)*1024 + (kc) + asg*8]); \
        cpa16(ab + ((arow+128)*PADK + asg*8)*2, \
              &A_h[(size_t)(m0 + arow + 128)*1024 + (kc) + asg*8]); \
        uint32_t bb2 = bDst0 + (buf)*PBN*PADK*2; \
        cpa16(bb2 + (brow*PADK + bsg*8)*2, \
              &B_h[(size_t)(n0 + brow)*1024 + (kc) + bsg*8]); \
        CPA_COMMIT(); \
    } while(0)

    LOAD_CHUNK(0, 0);

    for (int kk = 0; kk < 32; kk++){
        int buf = kk & 1;
        if (kk < 31){
            LOAD_CHUNK(buf^1, (kk+1)*32);
            CPA_WAIT1();
        } else {
            CPA_WAIT0();
        }
        __syncthreads();

        const uint32_t aBase = aDst0 + buf*PBM*PADK*2;
        const uint32_t bBase = bDst0 + buf*PBN*PADK*2;
        #pragma unroll
        for (int kf = 0; kf < 2; kf++){
            uint32_t a[4][4], b[4][2];
            int acol = kf*16 + ((lane & 16) ? 8 : 0);
            #pragma unroll
            for (int mf = 0; mf < 4; mf++){
                uint32_t addr = aBase + ((wm + mf*16 + (lane & 15))*PADK + acol)*2;
                LDSM_X4(a[mf][0], a[mf][1], a[mf][2], a[mf][3], addr);
            }
            int bcol = kf*16 + ((lane & 8) ? 8 : 0);
            #pragma unroll
            for (int nf = 0; nf < 4; nf++){
                uint32_t addr = bBase + ((wn + nf*8 + (lane & 7))*PADK + bcol)*2;
                LDSM_X2(b[nf][0], b[nf][1], addr);
            }
            #pragma unroll
            for (int mf = 0; mf < 4; mf++)
                #pragma unroll
                for (int nf = 0; nf < 4; nf++)
                    MMA16816(acc[mf][nf], a[mf], b[nf]);
        }
        __syncthreads();
    }

    const int g = lane >> 2, tg = lane & 3;
    #pragma unroll
    for (int nf = 0; nf < 4; nf++){
        int n = n0 + wn + nf*8 + tg*2;
        float b0 = bp[n], b1 = bp[n+1];
        #pragma unroll
        for (int mf = 0; mf < 4; mf++){
            int m = m0 + wm + mf*16 + g;
            if (m < OROWS){
                float2 st; st.x = acc[mf][nf][0] + b0; st.y = acc[mf][nf][1] + b1;
                *(float2*)&Cout[(size_t)m*V + n] = st;
            }
            if (m + 8 < OROWS){
                float2 st; st.x = acc[mf][nf][2] + b0; st.y = acc[mf][nf][3] + b1;
                *(float2*)&Cout[(size_t)(m+8)*V + n] = st;
            }
        }
    }
}

// ---------------- launch ----------------
extern "C" void kernel_launch(void* const* d_in, const int* in_sizes, int n_in,
                              void* d_out, int out_size)
{
    const int*   seqs  = (const int*)  d_in[0];
    const float* embed = (const float*)d_in[1];
    const float* fW0   = (const float*)d_in[2];
    const float* fU0   = (const float*)d_in[3];
    const float* fb0   = (const float*)d_in[4];
    const float* fW1   = (const float*)d_in[5];
    const float* fU1   = (const float*)d_in[6];
    const float* fb1   = (const float*)d_in[7];
    const float* bW0   = (const float*)d_in[8];
    const float* bU0   = (const float*)d_in[9];
    const float* bb0   = (const float*)d_in[10];
    const float* bW1   = (const float*)d_in[11];
    const float* bU1   = (const float*)d_in[12];
    const float* bb1   = (const float*)d_in[13];
    const float* Wp    = (const float*)d_in[14];
    const float* bp    = (const float*)d_in[15];
    float* out = (float*)d_out;

    const int RSMEM = RSMEM_FL * 4;
    cudaFuncSetAttribute(k_recur, cudaFuncAttributeMaxDynamicSharedMemorySize, RSMEM);
    cudaFuncSetAttribute(k_projhm, cudaFuncAttributeMaxDynamicSharedMemorySize, PJ_SMEM);

    k_init<<<(2*2*UH*BB + 255)/256, 256>>>();
    k_embed<<<(BB*TT*(D/4) + 255)/256, 256>>>(seqs, embed);

    dim3 gx(8, 16, 2);
    k_xprep<<<gx, 256>>>(fW0, fb0, bW0, bb0);

    dim3 gb(V/32, OC/32, 1);
    k_splitB<<<gb, 256>>>(Wp);

    k_recur<<<NBLK, 512, RSMEM>>>(fU0, fW1, fU1, fb1, bU0, bW1, bU1, bb1, seqs);

    dim3 gp(V/PBN, 2048/PBM, 1);
    k_projhm<<<gp, 512, PJ_SMEM>>>(bp, out);
}

// round 13
// speedup vs baseline: 1.0923x; 1.0923x over previous
#include <cuda_runtime.h>
#include <cuda_fp16.h>
#include <cstdint>
#include <math.h>

#define V   32000
#define D   256
#define UH  512
#define BB  16
#define TT  128
#define NS  126
#define G4  2048
#define OROWS (BB*NS)
#define OC  1024
#define NBLK 128
#define NSTEP 127

typedef unsigned long long ull;

// ---------------- device scratch ----------------
__device__ float g_emb[BB*TT*D];
__device__ float g_X[2][NS*BB*G4];
__device__ float g_h0t[2][2][UH*BB];
__device__ float g_h1t[2][2][UH*BB];
__device__ unsigned g_cnt2[2*32];
__device__ volatile unsigned g_gen2[2*32];
__device__ __half A_h[(size_t)2048*1024];     // [m][k]  (rows >= OROWS stay zero)
__device__ __half B_h[(size_t)32000*1024];    // [n][k]  (Wp^T)

// ---------------- f32x2 helpers ----------------
__device__ __forceinline__ ull pack2(float lo, float hi){
    ull r;
    asm("mov.b64 %0, {%1,%2};" : "=l"(r)
        : "r"(__float_as_uint(lo)), "r"(__float_as_uint(hi)));
    return r;
}
__device__ __forceinline__ void unpack2(ull v, float& lo, float& hi){
    unsigned a, b;
    asm("mov.b64 {%0,%1}, %2;" : "=r"(a), "=r"(b) : "l"(v));
    lo = __uint_as_float(a); hi = __uint_as_float(b);
}
__device__ __forceinline__ ull ffma2(ull a, ull b, ull c){
    ull r;
    asm("fma.rn.f32x2 %0, %1, %2, %3;" : "=l"(r) : "l"(a), "l"(b), "l"(c));
    return r;
}
__device__ __forceinline__ float sigf(float x){ return 1.f/(1.f + __expf(-x)); }
__device__ __forceinline__ float tanhfast(float x){ return 2.f/(1.f + __expf(-2.f*x)) - 1.f; }

// ---------------- arch-neutral PTX helpers ----------------
__device__ __forceinline__ uint32_t smem_u32(const void* p){
    uint32_t a;
    asm("{ .reg .u64 t; cvta.to.shared.u64 t, %1; cvt.u32.u64 %0, t; }" : "=r"(a) : "l"(p));
    return a;
}
__device__ __forceinline__ void cpa16(uint32_t s, const void* g){
    asm volatile("cp.async.cg.shared.global [%0], [%1], 16;" :: "r"(s), "l"(g) : "memory");
}
#define CPA_COMMIT() asm volatile("cp.async.commit_group;" ::: "memory")
#define CPA_WAIT1()  asm volatile("cp.async.wait_group 1;" ::: "memory")
#define CPA_WAIT0()  asm volatile("cp.async.wait_group 0;" ::: "memory")

#define LDSM_X4(r0,r1,r2,r3,addr) \
    asm volatile("ldmatrix.sync.aligned.m8n8.x4.shared.b16 {%0,%1,%2,%3}, [%4];" \
        : "=r"(r0), "=r"(r1), "=r"(r2), "=r"(r3) : "r"(addr))
#define LDSM_X2(r0,r1,addr) \
    asm volatile("ldmatrix.sync.aligned.m8n8.x2.shared.b16 {%0,%1}, [%2];" \
        : "=r"(r0), "=r"(r1) : "r"(addr))
#define MMA16816(c,a,b) \
    asm volatile("mma.sync.aligned.m16n8k16.row.col.f32.f16.f16.f32 " \
        "{%0,%1,%2,%3}, {%4,%5,%6,%7}, {%8,%9}, {%0,%1,%2,%3};" \
        : "+f"((c)[0]), "+f"((c)[1]), "+f"((c)[2]), "+f"((c)[3]) \
        : "r"((a)[0]), "r"((a)[1]), "r"((a)[2]), "r"((a)[3]), \
          "r"((b)[0]), "r"((b)[1]))

// ---------------- init (every replay) ----------------
__global__ void k_init(){
    int i = blockIdx.x*blockDim.x + threadIdx.x;
    int n = 2*2*UH*BB;
    if (i < n){
        ((float*)g_h0t)[i] = 0.f;
        ((float*)g_h1t)[i] = 0.f;
    }
    if (i < 64){ g_cnt2[i] = 0u; g_gen2[i] = 0u; }
}

// ---------------- embedding gather ----------------
__global__ void k_embed(const int* __restrict__ seqs, const float* __restrict__ embed){
    int i = blockIdx.x*blockDim.x + threadIdx.x;
    if (i >= BB*TT*(D/4)) return;
    int bt = i / (D/4);
    int d4 = i % (D/4);
    int tok = seqs[bt];
    float4 v = *(const float4*)&embed[(size_t)tok*D + d4*4];
    *(float4*)&g_emb[(size_t)bt*D + d4*4] = v;
}

// ---------------- X precompute GEMM (fp32 FFMA2) ----------------
__global__ __launch_bounds__(256) void k_xprep(const float* __restrict__ fW0,
                                               const float* __restrict__ fb0,
                                               const float* __restrict__ bW0,
                                               const float* __restrict__ bb0){
    const int dir = blockIdx.z;
    const float* W    = dir ? bW0 : fW0;
    const float* bias = dir ? bb0 : fb0;
    float* out = g_X[dir];
    const int m0 = blockIdx.y*128, n0 = blockIdx.x*256;
    __shared__ float As[16][128];
    __shared__ float Bs[16][256];
    const int tid = threadIdx.x;
    const int tx = tid & 15, ty = tid >> 4;

    ull acc[8][8];
    #pragma unroll
    for (int i=0;i<8;i++)
        #pragma unroll
        for (int q=0;q<8;q++) acc[i][q] = 0ull;

    for (int kt=0; kt<16; kt++){
        #pragma unroll
        for (int i=0;i<2;i++){
            int lin = tid + i*256;
            int row = lin>>2, c4 = lin&3;
            int r = m0 + row;
            float4 v = make_float4(0.f,0.f,0.f,0.f);
            if (r < OROWS){
                int t = r>>4, b = r&15;
                int txi = dir ? (127 - t) : t;
                v = *(const float4*)&g_emb[((b<<7)+txi)*D + kt*16 + c4*4];
            }
            As[c4*4+0][row]=v.x; As[c4*4+1][row]=v.y;
            As[c4*4+2][row]=v.z; As[c4*4+3][row]=v.w;
        }
        #pragma unroll
        for (int i=0;i<4;i++){
            int lin = tid + i*256;
            int kr = lin>>6, c4 = lin&63;
            *(float4*)&Bs[kr][c4*4] =
                *(const float4*)&W[(size_t)(kt*16+kr)*G4 + n0 + c4*4];
        }
        __syncthreads();
        #pragma unroll
        for (int k=0;k<16;k++){
            float a0[8];
            *(float4*)&a0[0] = *(float4*)&As[k][ty*8];
            *(float4*)&a0[4] = *(float4*)&As[k][ty*8+4];
            ull av[8];
            #pragma unroll
            for (int i=0;i<8;i++) av[i] = pack2(a0[i], a0[i]);
            ull bv[8];
            #pragma unroll
            for (int q=0;q<4;q++){
                ulonglong2 p = *(const ulonglong2*)&Bs[k][tx*16 + q*4];
                bv[2*q] = p.x; bv[2*q+1] = p.y;
            }
            #pragma unroll
            for (int i=0;i<8;i++)
                #pragma unroll
                for (int q=0;q<8;q++)
                    acc[i][q] = ffma2(av[i], bv[q], acc[i][q]);
        }
        __syncthreads();
    }
    #pragma unroll
    for (int i=0;i<8;i++){
        int r = m0 + ty*8 + i;
        if (r >= OROWS) continue;
        float* crow = out + (size_t)r*G4 + n0 + tx*16;
        #pragma unroll
        for (int q=0;q<8;q++){
            float lo,hi; unpack2(acc[i][q], lo, hi);
            int col = n0 + tx*16 + 2*q;
            float2 st; st.x = lo + bias[col]; st.y = hi + bias[col+1];
            *(float2*)&crow[2*q] = st;
        }
    }
}

// ---------------- persistent recurrence (R10 verbatim + bias hoist + Xp prefetch) ----------------
#define WSQ_FL   (8*1025*4)
#define HT_FL    (UH*BB)
#define ZP_FL    (8*32*8*2)
#define RSMEM_FL (WSQ_FL + 2*HT_FL + 2*ZP_FL + 256)

__global__ __launch_bounds__(256,1) void k_recur(
    const float* __restrict__ fU0, const float* __restrict__ fW1,
    const float* __restrict__ fU1, const float* __restrict__ fb1,
    const float* __restrict__ bU0, const float* __restrict__ bW1,
    const float* __restrict__ bU1, const float* __restrict__ bb1,
    const int*   __restrict__ seqs)
{
    extern __shared__ float sm[];
    float* wsQ  = sm;                          // [cq][k] float4 stride 1025
    float* ht0s = sm + WSQ_FL;                 // [k][16]
    float* ht1s = ht0s + HT_FL;
    float* zpAf = ht1s + HT_FL;                // [w][32][8][2]
    float* zpBf = zpAf + ZP_FL;
    float* c0s  = zpBf + ZP_FL;                // [128]
    float* c1s  = c0s + 128;
    ull* zpAu = (ull*)zpAf;
    ull* zpBu = (ull*)zpBf;

    const int tid  = threadIdx.x;
    const int wid  = tid >> 5;
    const int lane = tid & 31;
    const int blk  = blockIdx.x;
    const int dir  = blk >> 6;
    const int u0   = (blk & 63) * 8;

    const float* U0 = dir ? bU0 : fU0;
    const float* W1 = dir ? bW1 : fW1;
    const float* U1 = dir ? bU1 : fU1;
    const float* b1 = dir ? bb1 : fb1;
    const float* Xp = g_X[dir];

    // ---- preload U0|W1 into wsQ (once) ----
    for (int idx = tid; idx < 8*1024; idx += 256){
        int cq = idx >> 10, k = idx & 1023;
        int kk = k & 511;
        const float* Wsrc = (k < 512) ? U0 : W1;
        int jb = (cq>>1)*512 + u0 + (cq&1)*4;
        float4 v = *(const float4*)&Wsrc[(size_t)kk*G4 + jb];
        *(float4*)&wsQ[((size_t)cq*1025 + k)*4] = v;
    }
    if (tid < 128){ c0s[tid] = 0.f; c1s[tid] = 0.f; }
    __syncthreads();

    const int cq = lane & 7;          // col quad: cols 4cq..4cq+3
    const int bq = lane >> 3;         // batch quad: batches 4bq..4bq+3
    const int kbA = wid * 128;        // phase A weight k-range (0..1023)
    const int kA0 = kbA & 511;        // phase A h-index base (both halves read ht0s)
    const int kbB = wid * 64;         // phase B k-range (0..511)
    const float* wA = wsQ + ((size_t)cq*1025 + kbA)*4;
    const float* UgB = U1 + (size_t)((cq>>1)*512 + u0 + (cq&1)*4);
    const uint32_t d0s = smem_u32(ht0s);
    const uint32_t d1s = smem_u32(ht1s);
    unsigned* cnt = &g_cnt2[dir*32];
    volatile unsigned* gen = &g_gen2[dir*32];

    // hoisted activation constants (layer-1 bias is loop-invariant)
    const int act_uu = (tid & 127) >> 4;
    const int act_b  = tid & 15;
    float bias4[4];
    if (tid >= 128){
        #pragma unroll
        for (int g=0; g<4; g++) bias4[g] = b1[g*512 + u0 + act_uu];
    }

    for (int s = 0; s < NSTEP; s++){
        // ---- async-stage h0[s-1] (group A) and h1[s-2] (group B) ----
        {
            const float4* s0 = (const float4*)g_h0t[dir][(s+1)&1];
            const float4* s1 = (const float4*)g_h1t[dir][s&1];
            #pragma unroll
            for (int i=0;i<8;i++){ int ix = tid + i*256; cpa16(d0s + ix*16, s0+ix); }
            CPA_COMMIT();
            #pragma unroll
            for (int i=0;i<8;i++){ int ix = tid + i*256; cpa16(d1s + ix*16, s1+ix); }
            CPA_COMMIT();
        }

        // activation Xp prefetch (layer-0 threads) — latency hides under both phases
        float xv[4] = {0.f, 0.f, 0.f, 0.f};
        if (tid < 128 && s < NS){
            #pragma unroll
            for (int g=0; g<4; g++)
                xv[g] = __ldcg(&Xp[(size_t)((s<<4)+act_b)*G4 + g*512 + u0 + act_uu]);
        }

        // phase-B U1 group-0 prefetch (hides under staging + phase A)
        float4 wb0[8], wb1[8];
        #pragma unroll
        for (int i=0;i<8;i++)
            wb0[i] = __ldcg((const float4*)(UgB + (size_t)(kbB+i)*G4));

        CPA_WAIT1();            // ht0 resident (ht1 may still be in flight)
        __syncthreads();

        // ---- phase A: U0|W1 (smem weights), h0 (smem) ----
        ull accA[4][2];
        #pragma unroll
        for (int c=0;c<4;c++){ accA[c][0]=0ull; accA[c][1]=0ull; }
        {
            const float* hp = ht0s + (size_t)kA0*16 + bq*4;
            #pragma unroll 8
            for (int k=0;k<128;k++){
                float4 wv = *(const float4*)(wA + (size_t)k*4);
                ulonglong2 h2 = *(const ulonglong2*)(hp + (size_t)k*16);
                ull w0 = pack2(wv.x,wv.x), w1 = pack2(wv.y,wv.y);
                ull w2 = pack2(wv.z,wv.z), w3 = pack2(wv.w,wv.w);
                accA[0][0]=ffma2(w0,h2.x,accA[0][0]); accA[0][1]=ffma2(w0,h2.y,accA[0][1]);
                accA[1][0]=ffma2(w1,h2.x,accA[1][0]); accA[1][1]=ffma2(w1,h2.y,accA[1][1]);
                accA[2][0]=ffma2(w2,h2.x,accA[2][0]); accA[2][1]=ffma2(w2,h2.y,accA[2][1]);
                accA[3][0]=ffma2(w3,h2.x,accA[3][0]); accA[3][1]=ffma2(w3,h2.y,accA[3][1]);
            }
        }

        CPA_WAIT0();            // ht1 resident
        __syncthreads();

        // ---- phase B: U1 (gmem stream), h1 (smem) ----
        ull accB[4][2];
        #pragma unroll
        for (int c=0;c<4;c++){ accB[c][0]=0ull; accB[c][1]=0ull; }
        #pragma unroll
        for (int i=0;i<8;i++)
            wb1[i] = __ldcg((const float4*)(UgB + (size_t)(kbB+8+i)*G4));
        {
            const float* hp = ht1s + bq*4;
            #pragma unroll
            for (int g=0; g<8; g++){
                #pragma unroll
                for (int i=0;i<8;i++){
                    int k = kbB + g*8 + i;
                    float4 wv = (g&1) ? wb1[i] : wb0[i];
                    ulonglong2 h2 = *(const ulonglong2*)(hp + (size_t)k*16);
                    ull w0 = pack2(wv.x,wv.x), w1 = pack2(wv.y,wv.y);
                    ull w2 = pack2(wv.z,wv.z), w3 = pack2(wv.w,wv.w);
                    accB[0][0]=ffma2(w0,h2.x,accB[0][0]); accB[0][1]=ffma2(w0,h2.y,accB[0][1]);
                    accB[1][0]=ffma2(w1,h2.x,accB[1][0]); accB[1][1]=ffma2(w1,h2.y,accB[1][1]);
                    accB[2][0]=ffma2(w2,h2.x,accB[2][0]); accB[2][1]=ffma2(w2,h2.y,accB[2][1]);
                    accB[3][0]=ffma2(w3,h2.x,accB[3][0]); accB[3][1]=ffma2(w3,h2.y,accB[3][1]);
                    if (g < 6){
                        if (g&1) wb1[i] = __ldcg((const float4*)(UgB + (size_t)(k+16)*G4));
                        else     wb0[i] = __ldcg((const float4*)(UgB + (size_t)(k+16)*G4));
                    }
                }
            }
        }

        // ---- write partials ----
        #pragma unroll
        for (int c=0;c<4;c++){
            int col = cq*4 + c;
            #pragma unroll
            for (int p=0;p<2;p++){
                int bp = bq*2 + p;
                zpAu[((size_t)wid*32 + col)*8 + bp] = accA[c][p];
                zpBu[((size_t)wid*32 + col)*8 + bp] = accB[c][p];
            }
        }
        __syncthreads();

        // ---- activation / state update ----
        {
            int layer = tid >> 7, id = tid & 127;
            int uu = id >> 4, b = id & 15;
            int bp = b >> 1, par = b & 1;
            if (layer == 0){
                if (s < NS){
                    int t = s;
                    float z[4];
                    #pragma unroll
                    for (int g=0; g<4; g++){
                        int col = g*8 + uu;
                        float a = xv[g];
                        #pragma unroll
                        for (int w=0; w<4; w++)
                            a += zpAf[(((size_t)w*32 + col)*8 + bp)*2 + par];
                        z[g] = a;
                    }
                    float cold = c0s[id];
                    float cn = sigf(z[1])*cold + sigf(z[0])*tanhfast(z[2]);
                    float hn = sigf(z[3])*tanhfast(cn);
                    int pos = dir ? (127 - t) : t;
                    if (seqs[b*TT + pos] == 0){
                        cn = cold; hn = ht0s[(u0+uu)*16 + b];
                    }
                    c0s[id] = cn;
                    g_h0t[dir][s&1][(u0+uu)*16 + b] = hn;
                }
            } else {
                if (s >= 1){
                    int t = s - 1;
                    float z[4];
                    #pragma unroll
                    for (int g=0; g<4; g++){
                        int col = g*8 + uu;
                        float a = bias4[g];
                        #pragma unroll
                        for (int w=4; w<8; w++)
                            a += zpAf[(((size_t)w*32 + col)*8 + bp)*2 + par];
                        #pragma unroll
                        for (int w=0; w<8; w++)
                            a += zpBf[(((size_t)w*32 + col)*8 + bp)*2 + par];
                        z[g] = a;
                    }
                    float cold = c1s[id];
                    float cn = sigf(z[1])*cold + sigf(z[0])*tanhfast(z[2]);
                    float hn = sigf(z[3])*tanhfast(cn);
                    int pos = dir ? (127 - t) : t;
                    if (seqs[b*TT + pos] == 0){
                        cn = cold; hn = ht1s[(u0+uu)*16 + b];
                    }
                    c1s[id] = cn;
                    g_h1t[dir][(s+1)&1][(u0+uu)*16 + b] = hn;
                    // direct fp16 write into the projection A operand
                    int r = dir ? (b*NS + (125 - t)) : (b*NS + t);
                    A_h[(size_t)r*OC + dir*UH + u0 + uu] = __float2half_rn(hn);
                }
            }
        }

        // ---- per-direction grid barrier (64 blocks) ----
        __syncthreads();
        if (tid == 0){
            __threadfence();
            unsigned v = atomicAdd(cnt, 1u) + 1u;
            unsigned tgt = 64u * (unsigned)(s+1);
            if (v == tgt) *gen = (unsigned)(s+1);
            else while (*gen < (unsigned)(s+1)) __nanosleep(64);
        }
        __syncthreads();
    }
}

// ---------------- fp16 pack kernel for B ----------------
__global__ __launch_bounds__(256) void k_splitB(const float* __restrict__ Wp){
    __shared__ float tile[32][33];
    int n0 = blockIdx.x*32, k0 = blockIdx.y*32;
    int tx = threadIdx.x & 31, ty = threadIdx.x >> 5;
    #pragma unroll
    for (int i=0;i<4;i++){
        int k = k0 + ty + i*8;
        tile[ty+i*8][tx] = Wp[(size_t)k*V + n0 + tx];
    }
    __syncthreads();
    #pragma unroll
    for (int i=0;i<4;i++){
        int n = n0 + ty + i*8;
        float x = tile[tx][ty+i*8];
        B_h[(size_t)n*1024 + k0 + tx] = __float2half_rn(x);
    }
}

// ---------------- HMMA projection: single K=1024 GEMM ----------------
#define PBM 256
#define PBN 128
#define PADK 40
#define PA_FL (2*PBM*PADK)
#define PB_FL (2*PBN*PADK)
#define PJ_SMEM ((PA_FL + PB_FL)*2)

__global__ __launch_bounds__(512,1) void k_projhm(const float* __restrict__ bp,
                                                  float* __restrict__ Cout){
    extern __shared__ __half hsm[];
    __half* Asm = hsm;
    __half* Bsm = hsm + PA_FL;

    const int tid  = threadIdx.x;
    const int wid  = tid >> 5;
    const int lane = tid & 31;
    const int m0 = blockIdx.y * PBM, n0 = blockIdx.x * PBN;
    const int wm = (wid & 3) * 64;
    const int wn = (wid >> 2) * 32;

    float acc[4][4][4];
    #pragma unroll
    for (int mf=0; mf<4; mf++)
        #pragma unroll
        for (int nf=0; nf<4; nf++)
            #pragma unroll
            for (int i=0; i<4; i++) acc[mf][nf][i] = 0.f;

    const int arow = tid >> 2, asg = tid & 3;
    const int brow = tid >> 2, bsg = tid & 3;
    uint32_t aDst0 = smem_u32(Asm);
    uint32_t bDst0 = smem_u32(Bsm);

    #define LOAD_CHUNK(buf, kc) do { \
        uint32_t ab = aDst0 + (buf)*PBM*PADK*2; \
        cpa16(ab + (arow*PADK + asg*8)*2, \
              &A_h[(size_t)(m0 + arow)*1024 + (kc) + asg*8]); \
        cpa16(ab + ((arow+128)*PADK + asg*8)*2, \
              &A_h[(size_t)(m0 + arow + 128)*1024 + (kc) + asg*8]); \
        uint32_t bb2 = bDst0 + (buf)*PBN*PADK*2; \
        cpa16(bb2 + (brow*PADK + bsg*8)*2, \
              &B_h[(size_t)(n0 + brow)*1024 + (kc) + bsg*8]); \
        CPA_COMMIT(); \
    } while(0)

    LOAD_CHUNK(0, 0);

    for (int kk = 0; kk < 32; kk++){
        int buf = kk & 1;
        if (kk < 31){
            LOAD_CHUNK(buf^1, (kk+1)*32);
            CPA_WAIT1();
        } else {
            CPA_WAIT0();
        }
        __syncthreads();

        const uint32_t aBase = aDst0 + buf*PBM*PADK*2;
        const uint32_t bBase = bDst0 + buf*PBN*PADK*2;
        #pragma unroll
        for (int kf = 0; kf < 2; kf++){
            uint32_t a[4][4], b[4][2];
            int acol = kf*16 + ((lane & 16) ? 8 : 0);
            #pragma unroll
            for (int mf = 0; mf < 4; mf++){
                uint32_t addr = aBase + ((wm + mf*16 + (lane & 15))*PADK + acol)*2;
                LDSM_X4(a[mf][0], a[mf][1], a[mf][2], a[mf][3], addr);
            }
            int bcol = kf*16 + ((lane & 8) ? 8 : 0);
            #pragma unroll
            for (int nf = 0; nf < 4; nf++){
                uint32_t addr = bBase + ((wn + nf*8 + (lane & 7))*PADK + bcol)*2;
                LDSM_X2(b[nf][0], b[nf][1], addr);
            }
            #pragma unroll
            for (int mf = 0; mf < 4; mf++)
                #pragma unroll
                for (int nf = 0; nf < 4; nf++)
                    MMA16816(acc[mf][nf], a[mf], b[nf]);
        }
        __syncthreads();
    }

    const int g = lane >> 2, tg = lane & 3;
    #pragma unroll
    for (int nf = 0; nf < 4; nf++){
        int n = n0 + wn + nf*8 + tg*2;
        float b0 = bp[n], b1 = bp[n+1];
        #pragma unroll
        for (int mf = 0; mf < 4; mf++){
            int m = m0 + wm + mf*16 + g;
            if (m < OROWS){
                float2 st; st.x = acc[mf][nf][0] + b0; st.y = acc[mf][nf][1] + b1;
                *(float2*)&Cout[(size_t)m*V + n] = st;
            }
            if (m + 8 < OROWS){
                float2 st; st.x = acc[mf][nf][2] + b0; st.y = acc[mf][nf][3] + b1;
                *(float2*)&Cout[(size_t)(m+8)*V + n] = st;
            }
        }
    }
}

// ---------------- launch ----------------
extern "C" void kernel_launch(void* const* d_in, const int* in_sizes, int n_in,
                              void* d_out, int out_size)
{
    const int*   seqs  = (const int*)  d_in[0];
    const float* embed = (const float*)d_in[1];
    const float* fW0   = (const float*)d_in[2];
    const float* fU0   = (const float*)d_in[3];
    const float* fb0   = (const float*)d_in[4];
    const float* fW1   = (const float*)d_in[5];
    const float* fU1   = (const float*)d_in[6];
    const float* fb1   = (const float*)d_in[7];
    const float* bW0   = (const float*)d_in[8];
    const float* bU0   = (const float*)d_in[9];
    const float* bb0   = (const float*)d_in[10];
    const float* bW1   = (const float*)d_in[11];
    const float* bU1   = (const float*)d_in[12];
    const float* bb1   = (const float*)d_in[13];
    const float* Wp    = (const float*)d_in[14];
    const float* bp    = (const float*)d_in[15];
    float* out = (float*)d_out;

    const int RSMEM = RSMEM_FL * 4;
    cudaFuncSetAttribute(k_recur, cudaFuncAttributeMaxDynamicSharedMemorySize, RSMEM);
    cudaFuncSetAttribute(k_projhm, cudaFuncAttributeMaxDynamicSharedMemorySize, PJ_SMEM);

    // launch order puts k_recur in the slot ncu has been capturing
    k_init<<<(2*2*UH*BB + 255)/256, 256>>>();
    k_embed<<<(BB*TT*(D/4) + 255)/256, 256>>>(seqs, embed);

    dim3 gx(8, 16, 2);
    k_xprep<<<gx, 256>>>(fW0, fb0, bW0, bb0);

    k_recur<<<NBLK, 256, RSMEM>>>(fU0, fW1, fU1, fb1, bU0, bW1, bU1, bb1, seqs);

    dim3 gb(V/32, OC/32, 1);
    k_splitB<<<gb, 256>>>(Wp);

    dim3 gp(V/PBN, 2048/PBM, 1);
    k_projhm<<<gp, 512, PJ_SMEM>>>(bp, out);
}